// round 4
// baseline (speedup 1.0000x reference)
#include <cuda_runtime.h>
#include <cstdint>
#include <cstddef>

// Problem dims
#define Bn 64
#define Tn 2048
#define Fn 256
#define Hn 512
#define On 128

// Fused recurrence partition: 16 groups x 4 batches, 8 slices x 64 cols = 128 CTAs
#define NG 16
#define GB 4
#define NS 8
#define SC 64
#define NKG 8
#define KC 64
#define NCOMP 512
#define NTHR 544          // 16 compute warps + 1 comm warp
#define WSTRIDE 516       // padded W_ih1 row stride (floats)

#define HB (GB * Hn * 4)  // 8192 bytes per hidden-state exchange

// ---------------- static device workspaces -------------------------------------
__device__ __align__(128) float g_xp[(size_t)Bn * Tn * Hn];      // 256 MB input proj
__device__ __align__(128) float g_h0buf[2][NG][GB * Hn];
__device__ __align__(128) float g_h1buf[2][NG][GB * Hn];
__device__ __align__(128) float g_hT[Bn * Hn];
__device__ unsigned g_flags0[NG][NS];
__device__ unsigned g_flags1[NG][NS];

typedef unsigned long long u64t;

// ---------------- packed fp32x2 + sync helpers ----------------------------------
__device__ __forceinline__ u64t fma2(u64t a, u64t b, u64t c) {
    u64t d;
    asm("fma.rn.f32x2 %0, %1, %2, %3;" : "=l"(d) : "l"(a), "l"(b), "l"(c));
    return d;
}
__device__ __forceinline__ u64t pk2(float lo, float hi) {
    u64t r;
    asm("mov.b64 %0, {%1, %2};" : "=l"(r) : "f"(lo), "f"(hi));
    return r;
}
__device__ __forceinline__ float2 upk(u64t v) {
    float2 f;
    asm("mov.b64 {%0, %1}, %2;" : "=f"(f.x), "=f"(f.y) : "l"(v));
    return f;
}
__device__ __forceinline__ unsigned ld_acq(const unsigned* p) {
    unsigned v;
    asm volatile("ld.global.acquire.gpu.u32 %0, [%1];" : "=r"(v) : "l"(p));
    return v;
}
__device__ __forceinline__ void st_rel(unsigned* p, unsigned v) {
    asm volatile("st.global.release.gpu.u32 [%0], %1;" :: "l"(p), "r"(v) : "memory");
}
__device__ __forceinline__ unsigned smem_u32(const void* p) {
    unsigned a;
    asm("{ .reg .u64 t; cvta.to.shared.u64 t, %1; cvt.u32.u64 %0, t; }" : "=r"(a) : "l"(p));
    return a;
}
__device__ __forceinline__ void mbar_init(unsigned m, unsigned cnt) {
    asm volatile("mbarrier.init.shared.b64 [%0], %1;" :: "r"(m), "r"(cnt) : "memory");
}
__device__ __forceinline__ void mbar_expect_tx(unsigned m, unsigned bytes) {
    asm volatile("mbarrier.arrive.expect_tx.shared.b64 _, [%0], %1;" :: "r"(m), "r"(bytes) : "memory");
}
__device__ __forceinline__ void bulk_g2s(unsigned dst, const void* src, unsigned bytes, unsigned m) {
    asm volatile("cp.async.bulk.shared::cluster.global.mbarrier::complete_tx::bytes [%0], [%1], %2, [%3];"
                 :: "r"(dst), "l"(src), "r"(bytes), "r"(m) : "memory");
}
__device__ __forceinline__ void mbar_wait(unsigned m, int phase) {
    asm volatile(
        "{\n\t.reg .pred P;\n"
        "WL%=:\n\t"
        "mbarrier.try_wait.parity.acquire.cta.shared::cta.b64 P, [%0], %1, 0x989680;\n\t"
        "@P bra WD%=;\n\t"
        "bra WL%=;\n"
        "WD%=:\n\t}"
        :: "r"(m), "r"((unsigned)phase) : "memory");
}
__device__ __forceinline__ void bar_sync(int id, int cnt) {
    asm volatile("bar.sync %0, %1;" :: "r"(id), "r"(cnt) : "memory");
}
__device__ __forceinline__ void bar_arrive(int id, int cnt) {
    asm volatile("bar.arrive %0, %1;" :: "r"(id), "r"(cnt) : "memory");
}

// ---------------- GEMM1: g_xp[M,512] = x[M,256] * W_ih0[512,256]^T + b ----------
__global__ __launch_bounds__(256) void sgemm_xp(
    const float* __restrict__ A, const float* __restrict__ Wm,
    const float* __restrict__ b1, const float* __restrict__ b2)
{
    __shared__ float As[8][128];
    __shared__ float Ws[8][128];

    const int tid = threadIdx.x;
    if (blockIdx.x == 0 && blockIdx.y == 0 && tid < NG * NS) {
        ((unsigned*)g_flags0)[tid] = 0u;
        ((unsigned*)g_flags1)[tid] = 0u;
    }

    const int K = Fn;
    const int bm = blockIdx.x, bn = blockIdx.y;
    const int row = tid >> 1;
    const int kq = (tid & 1) * 4;
    const float* Ag = A + (size_t)(bm * 128 + row) * K + kq;
    const float* Wg = Wm + (size_t)(bn * 128 + row) * K + kq;
    const int tx = tid & 15, ty = tid >> 4;
    const int m0 = ty * 8, n0 = tx * 8;

    u64t acc[8][4];
#pragma unroll
    for (int i = 0; i < 8; i++)
#pragma unroll
        for (int j = 0; j < 4; j++) acc[i][j] = 0ull;

    float4 ap = *(const float4*)Ag;
    float4 wp = *(const float4*)Wg;
    const int nk = K >> 3;

    for (int kt = 0; kt < nk; kt++) {
        As[kq + 0][row] = ap.x; As[kq + 1][row] = ap.y;
        As[kq + 2][row] = ap.z; As[kq + 3][row] = ap.w;
        Ws[kq + 0][row] = wp.x; Ws[kq + 1][row] = wp.y;
        Ws[kq + 2][row] = wp.z; Ws[kq + 3][row] = wp.w;
        __syncthreads();
        if (kt + 1 < nk) {
            ap = *(const float4*)(Ag + (size_t)(kt + 1) * 8);
            wp = *(const float4*)(Wg + (size_t)(kt + 1) * 8);
        }
#pragma unroll
        for (int k = 0; k < 8; k++) {
            float4 a0 = *(const float4*)&As[k][m0];
            float4 a1 = *(const float4*)&As[k][m0 + 4];
            const u64t* bp = (const u64t*)&Ws[k][n0];
            u64t bv0 = bp[0], bv1 = bp[1], bv2 = bp[2], bv3 = bp[3];
            float av[8] = {a0.x, a0.y, a0.z, a0.w, a1.x, a1.y, a1.z, a1.w};
#pragma unroll
            for (int i = 0; i < 8; i++) {
                u64t ai = pk2(av[i], av[i]);
                acc[i][0] = fma2(ai, bv0, acc[i][0]);
                acc[i][1] = fma2(ai, bv1, acc[i][1]);
                acc[i][2] = fma2(ai, bv2, acc[i][2]);
                acc[i][3] = fma2(ai, bv3, acc[i][3]);
            }
        }
        __syncthreads();
    }

    const int gn = bn * 128 + n0;
    float bs[8];
#pragma unroll
    for (int j = 0; j < 8; j++) bs[j] = b1[gn + j] + b2[gn + j];
#pragma unroll
    for (int i = 0; i < 8; i++) {
        float* cp = g_xp + (size_t)(bm * 128 + m0 + i) * Hn + gn;
        float2 p0 = upk(acc[i][0]), p1 = upk(acc[i][1]);
        float2 p2 = upk(acc[i][2]), p3 = upk(acc[i][3]);
        *(float4*)cp       = make_float4(p0.x + bs[0], p0.y + bs[1], p1.x + bs[2], p1.y + bs[3]);
        *(float4*)(cp + 4) = make_float4(p2.x + bs[4], p2.y + bs[5], p3.x + bs[6], p3.y + bs[7]);
    }
}

// ---------------- fused two-layer recurrence, warp-specialized ------------------
// Step t: phase A computes h0_t (needs h0_{t-1}); phase B computes h1_{t-1}
// (needs h1_{t-2}, h0_{t-1}). All inputs were published in step t-1, so the
// comm warp's poll->TMA chains hide under compute. Compute warps execute only
// bar.sync; the comm warp owns flags polls, TMA issue, and mbarrier waits, and
// releases buffers via bar.arrive (barriers 1 = h0 ready, 2 = h1 ready).
__global__ __launch_bounds__(NTHR, 1) void fused_rnn(
    const float* __restrict__ Whh0, const float* __restrict__ Wih1,
    const float* __restrict__ Whh1,
    const float* __restrict__ bih1, const float* __restrict__ bhh1,
    const float* __restrict__ h00, const float* __restrict__ h01)
{
    extern __shared__ float sm[];
    float* wih1  = sm;                   // SC*WSTRIDE = 33024 floats
    float* shh0  = sm + SC * WSTRIDE;    // 2 x GB*Hn (parity)
    float* shh1  = shh0 + 2 * GB * Hn;   // 2 x GB*Hn
    float* part0 = shh1 + 2 * GB * Hn;   // NKG * 256
    float* part1 = part0 + NKG * 256;    // NKG * 256
    __shared__ __align__(8) unsigned long long mbar[2];

    const int tid = threadIdx.x;
    const int slice = blockIdx.x & (NS - 1);
    const int group = blockIdx.x >> 3;
    const bool comm = (tid >= NCOMP);
    const int j = tid & 63;
    const int kg = (tid >> 6) & 7;
    const int kb = kg * KC;

    // compute warps: recurrence weights into registers (64 floats per matrix)
    u64t w0[32], w1[32];
    if (!comm) {
        const int col = slice * SC + j;
        const ulonglong2* p0 = (const ulonglong2*)(Whh0 + (size_t)col * Hn + kb);
        const ulonglong2* p1 = (const ulonglong2*)(Whh1 + (size_t)col * Hn + kb);
#pragma unroll
        for (int i = 0; i < 16; i++) {
            ulonglong2 a = p0[i]; w0[2 * i] = a.x; w0[2 * i + 1] = a.y;
            ulonglong2 b = p1[i]; w1[2 * i] = b.x; w1[2 * i + 1] = b.y;
        }
    }
    // W_ih1 slice into padded SMEM (all threads help)
    for (int idx = tid; idx < SC * Hn; idx += NTHR) {
        int r = idx >> 9, k = idx & 511;
        wih1[r * WSTRIDE + k] = Wih1[(size_t)(slice * SC + r) * Hn + k];
    }
    // preload: shh0 parity0 = h00 (step 0); shh1 parity1 = h01 (step 1)
    for (int idx = tid; idx < GB * Hn; idx += NTHR) {
        shh0[idx] = h00[idx & 511];
        shh1[GB * Hn + idx] = h01[idx & 511];
    }

    const unsigned mb0 = smem_u32(&mbar[0]);
    const unsigned mb1 = smem_u32(&mbar[1]);
    const unsigned sh0a = smem_u32(shh0);
    const unsigned sh1a = smem_u32(shh1);
    if (tid == 0) {
        mbar_init(mb0, 1);
        mbar_init(mb1, 1);
        asm volatile("fence.proxy.async.shared::cta;" ::: "memory");
    }

    // reduce role (compute tid < 256): (batch rb, col rj)
    const int rb = tid >> 6, rj = tid & 63;
    const int rcol = slice * SC + rj;
    const float bias1 = bih1[rcol] + bhh1[rcol];
    const size_t xbase = ((size_t)(group * GB + rb) * Tn) * Hn + rcol;
    float xpv = (tid < 256) ? __ldg(g_xp + xbase) : 0.f;
    unsigned* f0g = &g_flags0[group][0];
    unsigned* f1g = &g_flags1[group][0];
    __syncthreads();

    if (comm) {
        // ---------------- communication warp ----------------
        const int lane = tid - NCOMP;
        int ph0 = 0, ph1 = 0;
#pragma unroll 1
        for (int t = 0; t <= Tn; t++) {
            const int cur = t & 1, nxt = cur ^ 1;
            // release shh0[cur] (h0_{t-1})
            if (t > 0) {
                if (lane == 0) mbar_wait(mb0, ph0);
                __syncwarp();
                ph0 ^= 1;
            }
            bar_arrive(1, NTHR);
            // release shh1[cur] (h1_{t-2})
            if (t >= 1) {
                if (t >= 2) {
                    if (lane == 0) mbar_wait(mb1, ph1);
                    __syncwarp();
                    ph1 ^= 1;
                }
                bar_arrive(2, NTHR);
            }
            if (t < Tn) {
                // TMA0: h0_t -> shh0[nxt] (h0_t published mid-step t)
                if (lane < NS) { while (ld_acq(&f0g[lane]) < (unsigned)(t + 1)) {} }
                __syncwarp();
                if (lane == 0) {
                    mbar_expect_tx(mb0, HB);
                    bulk_g2s(sh0a + nxt * HB, &g_h0buf[cur][group][0], HB, mb0);
                }
                // TMA1: h1_{t-1} -> shh1[nxt] (published end of step t)
                if (t >= 1) {
                    if (lane < NS) { while (ld_acq(&f1g[lane]) < (unsigned)t) {} }
                    __syncwarp();
                    if (lane == 0) {
                        mbar_expect_tx(mb1, HB);
                        bulk_g2s(sh1a + nxt * HB, &g_h1buf[cur][group][0], HB, mb1);
                    }
                }
            }
        }
        return;
    }

    // ---------------- compute warps ----------------
    u64t acc[GB];
#pragma unroll 1
    for (int t = 0; t <= Tn; t++) {
        const int cur = t & 1;
        const float* h0c = shh0 + cur * (GB * Hn);
        const float* h1c = shh1 + cur * (GB * Hn);

        bar_sync(1, NTHR);   // shh0[cur] = h0_{t-1} ready

        if (t < Tn) {
            // ---- phase A: mv0 = W_hh0 . h0_{t-1}
#pragma unroll
            for (int b = 0; b < GB; b++) acc[b] = 0ull;
#pragma unroll
            for (int ii = 0; ii < 16; ii++) {
#pragma unroll
                for (int b = 0; b < GB; b++) {
                    ulonglong2 h2 = *(const ulonglong2*)(h0c + b * Hn + kb + ii * 4);
                    acc[b] = fma2(w0[2 * ii],     h2.x, acc[b]);
                    acc[b] = fma2(w0[2 * ii + 1], h2.y, acc[b]);
                }
            }
#pragma unroll
            for (int b = 0; b < GB; b++) {
                float2 f = upk(acc[b]);
                part0[kg * 256 + b * 64 + j] = f.x + f.y;
            }
            bar_sync(3, NCOMP);
            if (tid < 256) {
                float s0 = xpv, s1 = 0.f;
#pragma unroll
                for (int kk = 0; kk < NKG; kk += 2) {
                    s0 += part0[kk * 256 + tid];
                    s1 += part0[(kk + 1) * 256 + tid];
                }
                float hn = tanhf(s0 + s1);
                __stcg(&g_h0buf[cur][group][rb * Hn + rcol], hn);
                if (t + 1 < Tn) xpv = __ldg(g_xp + xbase + (size_t)(t + 1) * Hn);
            }
            bar_sync(3, NCOMP);
            if (tid == 0) st_rel(&f0g[slice], (unsigned)(t + 1));
        }

        if (t >= 1) {
            bar_sync(2, NTHR);   // shh1[cur] = h1_{t-2} ready

            // ---- phase B: mvB = W_hh1 . h1_{t-2}
#pragma unroll
            for (int b = 0; b < GB; b++) acc[b] = 0ull;
#pragma unroll
            for (int ii = 0; ii < 16; ii++) {
#pragma unroll
                for (int b = 0; b < GB; b++) {
                    ulonglong2 h2 = *(const ulonglong2*)(h1c + b * Hn + kb + ii * 4);
                    acc[b] = fma2(w1[2 * ii],     h2.x, acc[b]);
                    acc[b] = fma2(w1[2 * ii + 1], h2.y, acc[b]);
                }
            }
            // ---- mvC = W_ih1 . h0_{t-1}
            {
                const float* wr = wih1 + j * WSTRIDE + kb;
#pragma unroll
                for (int ii = 0; ii < 16; ii++) {
                    ulonglong2 w2 = *(const ulonglong2*)(wr + ii * 4);
#pragma unroll
                    for (int b = 0; b < GB; b++) {
                        ulonglong2 h2 = *(const ulonglong2*)(h0c + b * Hn + kb + ii * 4);
                        acc[b] = fma2(w2.x, h2.x, acc[b]);
                        acc[b] = fma2(w2.y, h2.y, acc[b]);
                    }
                }
            }
#pragma unroll
            for (int b = 0; b < GB; b++) {
                float2 f = upk(acc[b]);
                part1[kg * 256 + b * 64 + j] = f.x + f.y;
            }
            bar_sync(3, NCOMP);
            if (tid < 256) {
                float s0 = bias1, s1 = 0.f;
#pragma unroll
                for (int kk = 0; kk < NKG; kk += 2) {
                    s0 += part1[kk * 256 + tid];
                    s1 += part1[(kk + 1) * 256 + tid];
                }
                float hn = tanhf(s0 + s1);
                if (t < Tn) __stcg(&g_h1buf[cur][group][rb * Hn + rcol], hn);
                else        g_hT[(group * GB + rb) * Hn + rcol] = hn;
            }
            bar_sync(3, NCOMP);
            if (t < Tn && tid == 0) st_rel(&f1g[slice], (unsigned)t);
        }
    }
}

// ---------------- final FC ------------------------------------------------------
__global__ __launch_bounds__(128) void fc_kernel(
    const float* __restrict__ Wfc, const float* __restrict__ bfc,
    float* __restrict__ out)
{
    __shared__ float hs[Hn];
    const int b = blockIdx.x, tid = threadIdx.x;
    ((float4*)hs)[tid] = *(const float4*)&g_hT[b * Hn + tid * 4];
    __syncthreads();
    const float4* wr = (const float4*)(Wfc + (size_t)tid * Hn);
    float acc = 0.f;
#pragma unroll 8
    for (int i = 0; i < Hn / 4; i++) {
        float4 w = __ldg(&wr[i]);
        float4 h = ((const float4*)hs)[i];
        acc += w.x * h.x + w.y * h.y + w.z * h.z + w.w * h.w;
    }
    out[b * On + tid] = acc + bfc[tid];
}

// ---------------- launcher ------------------------------------------------------
extern "C" void kernel_launch(void* const* d_in, const int* in_sizes, int n_in,
                              void* d_out, int out_size)
{
    (void)in_sizes; (void)n_in; (void)out_size;
    const float* x     = (const float*)d_in[0];
    const float* W_ih0 = (const float*)d_in[1];
    const float* W_hh0 = (const float*)d_in[2];
    const float* b_ih0 = (const float*)d_in[3];
    const float* b_hh0 = (const float*)d_in[4];
    const float* h0_0  = (const float*)d_in[5];
    const float* W_ih1 = (const float*)d_in[6];
    const float* W_hh1 = (const float*)d_in[7];
    const float* b_ih1 = (const float*)d_in[8];
    const float* b_hh1 = (const float*)d_in[9];
    const float* h0_1  = (const float*)d_in[10];
    const float* W_fc  = (const float*)d_in[11];
    const float* b_fc  = (const float*)d_in[12];
    float* out = (float*)d_out;

    const int fused_smem =
        (SC * WSTRIDE + 4 * GB * Hn + 2 * NKG * 256) * sizeof(float);
    cudaFuncSetAttribute(fused_rnn, cudaFuncAttributeMaxDynamicSharedMemorySize, fused_smem);

    // xp0 = x @ W_ih0^T + b_ih0 + b_hh0  (block 0 also resets exchange flags)
    sgemm_xp<<<dim3((Bn * Tn) / 128, Hn / 128), 256>>>(x, W_ih0, b_ih0, b_hh0);

    // fused skewed two-layer recurrence, warp-specialized comm
    fused_rnn<<<NG * NS, NTHR, fused_smem>>>(W_hh0, W_ih1, W_hh1,
                                             b_ih1, b_hh1, h0_0, h0_1);

    // head
    fc_kernel<<<Bn, 128>>>(W_fc, b_fc, out);
}

// round 5
// speedup vs baseline: 1.2307x; 1.2307x over previous
#include <cuda_runtime.h>
#include <cstdint>
#include <cstddef>

// Problem dims
#define Bn 64
#define Tn 2048
#define Fn 256
#define Hn 512
#define On 128

// Partition: 8 groups x 8 batches; 16 slices x 32 cols; cluster = 16 CTAs = 1 group
#define NG 8
#define GB 8
#define NS 16
#define SC 32
#define NTHR 512
#define WSTRIDE 516
#define SLOTF 4096          // floats per hidden slot: [16 slices][8 b][32 cols]
#define SLOTB 16384         // bytes
#define REGB 1024           // bytes per CTA region (8b x 32 cols x 4B)
#define EXPTX (15 * REGB)   // expected tx per phase

// ---------------- static device workspaces -------------------------------------
__device__ __align__(128) float g_xp[(size_t)Bn * Tn * Hn];   // 256 MB input proj
__device__ __align__(128) float g_hT[Bn * Hn];

typedef unsigned long long u64t;

// ---------------- packed fp32x2 + cluster helpers -------------------------------
__device__ __forceinline__ u64t fma2(u64t a, u64t b, u64t c) {
    u64t d;
    asm("fma.rn.f32x2 %0, %1, %2, %3;" : "=l"(d) : "l"(a), "l"(b), "l"(c));
    return d;
}
__device__ __forceinline__ u64t pk2(float lo, float hi) {
    u64t r;
    asm("mov.b64 %0, {%1, %2};" : "=l"(r) : "f"(lo), "f"(hi));
    return r;
}
__device__ __forceinline__ float2 upk(u64t v) {
    float2 f;
    asm("mov.b64 {%0, %1}, %2;" : "=f"(f.x), "=f"(f.y) : "l"(v));
    return f;
}
__device__ __forceinline__ unsigned smem_u32(const void* p) {
    unsigned a;
    asm("{ .reg .u64 t; cvta.to.shared.u64 t, %1; cvt.u32.u64 %0, t; }" : "=r"(a) : "l"(p));
    return a;
}
__device__ __forceinline__ unsigned mapa_u32(unsigned a, unsigned r) {
    unsigned d;
    asm("mapa.shared::cluster.u32 %0, %1, %2;" : "=r"(d) : "r"(a), "r"(r));
    return d;
}
__device__ __forceinline__ void mbar_init(unsigned m, unsigned cnt) {
    asm volatile("mbarrier.init.shared.b64 [%0], %1;" :: "r"(m), "r"(cnt) : "memory");
}
__device__ __forceinline__ void mbar_expect(unsigned m, unsigned bytes) {
    asm volatile("mbarrier.arrive.expect_tx.shared.b64 _, [%0], %1;" :: "r"(m), "r"(bytes) : "memory");
}
__device__ __forceinline__ void bulk_s2s(unsigned dst, unsigned src, unsigned bytes, unsigned mbar) {
    asm volatile("cp.async.bulk.shared::cluster.shared::cta.mbarrier::complete_tx::bytes [%0], [%1], %2, [%3];"
                 :: "r"(dst), "r"(src), "r"(bytes), "r"(mbar) : "memory");
}
__device__ __forceinline__ void mbar_waitc(unsigned m, unsigned ph) {
    asm volatile(
        "{\n\t.reg .pred P;\n"
        "WL%=:\n\t"
        "mbarrier.try_wait.parity.acquire.cluster.shared::cta.b64 P, [%0], %1, 0x989680;\n\t"
        "@P bra WD%=;\n\t"
        "bra WL%=;\n"
        "WD%=:\n\t}"
        :: "r"(m), "r"(ph) : "memory");
}
__device__ __forceinline__ void fence_async() {
    asm volatile("fence.proxy.async.shared::cta;" ::: "memory");
}
__device__ __forceinline__ void cluster_sync() {
    asm volatile("barrier.cluster.arrive.aligned;" ::: "memory");
    asm volatile("barrier.cluster.wait.aligned;" ::: "memory");
}

// ---------------- GEMM1: g_xp[M,512] = x[M,256] * W_ih0[512,256]^T + b ----------
__global__ __launch_bounds__(256) void sgemm_xp(
    const float* __restrict__ A, const float* __restrict__ Wm,
    const float* __restrict__ b1, const float* __restrict__ b2)
{
    __shared__ float As[8][128];
    __shared__ float Ws[8][128];

    const int tid = threadIdx.x;
    const int K = Fn;
    const int bm = blockIdx.x, bn = blockIdx.y;
    const int row = tid >> 1;
    const int kq = (tid & 1) * 4;
    const float* Ag = A + (size_t)(bm * 128 + row) * K + kq;
    const float* Wg = Wm + (size_t)(bn * 128 + row) * K + kq;
    const int tx = tid & 15, ty = tid >> 4;
    const int m0 = ty * 8, n0 = tx * 8;

    u64t acc[8][4];
#pragma unroll
    for (int i = 0; i < 8; i++)
#pragma unroll
        for (int j = 0; j < 4; j++) acc[i][j] = 0ull;

    float4 ap = *(const float4*)Ag;
    float4 wp = *(const float4*)Wg;
    const int nk = K >> 3;

    for (int kt = 0; kt < nk; kt++) {
        As[kq + 0][row] = ap.x; As[kq + 1][row] = ap.y;
        As[kq + 2][row] = ap.z; As[kq + 3][row] = ap.w;
        Ws[kq + 0][row] = wp.x; Ws[kq + 1][row] = wp.y;
        Ws[kq + 2][row] = wp.z; Ws[kq + 3][row] = wp.w;
        __syncthreads();
        if (kt + 1 < nk) {
            ap = *(const float4*)(Ag + (size_t)(kt + 1) * 8);
            wp = *(const float4*)(Wg + (size_t)(kt + 1) * 8);
        }
#pragma unroll
        for (int k = 0; k < 8; k++) {
            float4 a0 = *(const float4*)&As[k][m0];
            float4 a1 = *(const float4*)&As[k][m0 + 4];
            const u64t* bp = (const u64t*)&Ws[k][n0];
            u64t bv0 = bp[0], bv1 = bp[1], bv2 = bp[2], bv3 = bp[3];
            float av[8] = {a0.x, a0.y, a0.z, a0.w, a1.x, a1.y, a1.z, a1.w};
#pragma unroll
            for (int i = 0; i < 8; i++) {
                u64t ai = pk2(av[i], av[i]);
                acc[i][0] = fma2(ai, bv0, acc[i][0]);
                acc[i][1] = fma2(ai, bv1, acc[i][1]);
                acc[i][2] = fma2(ai, bv2, acc[i][2]);
                acc[i][3] = fma2(ai, bv3, acc[i][3]);
            }
        }
        __syncthreads();
    }

    const int gn = bn * 128 + n0;
    float bs[8];
#pragma unroll
    for (int j = 0; j < 8; j++) bs[j] = b1[gn + j] + b2[gn + j];
#pragma unroll
    for (int i = 0; i < 8; i++) {
        float* cp = g_xp + (size_t)(bm * 128 + m0 + i) * Hn + gn;
        float2 p0 = upk(acc[i][0]), p1 = upk(acc[i][1]);
        float2 p2 = upk(acc[i][2]), p3 = upk(acc[i][3]);
        *(float4*)cp       = make_float4(p0.x + bs[0], p0.y + bs[1], p1.x + bs[2], p1.y + bs[3]);
        *(float4*)(cp + 4) = make_float4(p2.x + bs[4], p2.y + bs[5], p3.x + bs[6], p3.y + bs[7]);
    }
}

// ---------------- fused two-layer recurrence: 16-CTA cluster DSMEM exchange -----
// Hidden slots are slice-major [16 slices][8 batches][32 cols] so each CTA's
// contribution is one contiguous 1KB block, pushed to all 15 peers with
// cp.async.bulk.shared::cluster (mbarrier complete_tx). Step t computes h0_t
// (phase A, from h0_{t-1}) and h1_{t-1} (phase B, from h1_{t-2} + h0_{t-1}).
__global__ __launch_bounds__(NTHR, 1) __cluster_dims__(NS, 1, 1)
void fused_rnn(
    const float* __restrict__ Whh0, const float* __restrict__ Wih1,
    const float* __restrict__ Whh1,
    const float* __restrict__ bih1, const float* __restrict__ bhh1,
    const float* __restrict__ h00, const float* __restrict__ h01)
{
    extern __shared__ float sm[];
    float* wih1  = sm;                    // SC*WSTRIDE = 16512 floats
    float* shh0  = sm + SC * WSTRIDE;     // 2 x SLOTF (parity)
    float* shh1  = shh0 + 2 * SLOTF;      // 2 x SLOTF
    float* part0 = shh1 + 2 * SLOTF;      // 16*256 = 4096
    float* part1 = part0 + SLOTF;         // 4096
    __shared__ __align__(8) unsigned long long mb0[2], mb1[2];

    const int tid = threadIdx.x;
    const int slice = blockIdx.x & (NS - 1);   // rank within cluster
    const int group = blockIdx.x >> 4;
    const int j = tid & 31;
    const int kg = tid >> 5;                   // [0,16): K-chunk == source slice
    const int col = slice * SC + j;

    // recurrence weight chunks into registers (32 floats per matrix per thread)
    u64t w0[16], w1[16];
    {
        const ulonglong2* p0 = (const ulonglong2*)(Whh0 + (size_t)col * Hn + kg * 32);
        const ulonglong2* p1 = (const ulonglong2*)(Whh1 + (size_t)col * Hn + kg * 32);
#pragma unroll
        for (int i = 0; i < 8; i++) {
            ulonglong2 a = p0[i]; w0[2 * i] = a.x; w0[2 * i + 1] = a.y;
            ulonglong2 b = p1[i]; w1[2 * i] = b.x; w1[2 * i + 1] = b.y;
        }
    }
    // W_ih1 slice rows into padded SMEM
    for (int idx = tid; idx < SC * Hn; idx += NTHR) {
        int r = idx >> 9, k = idx & 511;
        wih1[r * WSTRIDE + k] = Wih1[(size_t)(slice * SC + r) * Hn + k];
    }
    // preload hidden slots (slice-major): slot0 of h0 = h00; slot1 of h1 = h01
    for (int idx = tid; idx < SLOTF; idx += NTHR) {
        int s = idx >> 8, jj = idx & 31;
        shh0[idx] = h00[s * 32 + jj];
        shh1[SLOTF + idx] = h01[s * 32 + jj];
    }

    const unsigned mb0a = smem_u32(&mb0[0]);
    const unsigned mb1a = smem_u32(&mb1[0]);
    const unsigned sh0a = smem_u32(shh0);
    const unsigned sh1a = smem_u32(shh1);
    if (tid == 0) {
        mbar_init(mb0a, 1);     mbar_init(mb0a + 8, 1);
        mbar_init(mb1a, 1);     mbar_init(mb1a + 8, 1);
        mbar_expect(mb0a, EXPTX);     mbar_expect(mb0a + 8, EXPTX);
        mbar_expect(mb1a, EXPTX);     mbar_expect(mb1a + 8, EXPTX);
    }
    // reducer role (tid<256): batch rb, col rj
    const int rb = tid >> 5, rj = tid & 31;
    const int rcol = slice * SC + rj;
    const float bias1 = bih1[rcol] + bhh1[rcol];
    const size_t xbase = ((size_t)(group * GB + rb) * Tn) * Hn + rcol;
    float xpv = (tid < 256) ? __ldg(g_xp + xbase) : 0.f;
    __syncthreads();
    cluster_sync();   // all mbarriers armed cluster-wide before any bulk push

    // peer rank for the 15 senders (skip self)
    const unsigned prank = (unsigned)tid + ((tid >= slice) ? 1u : 0u);

    unsigned ph0[2] = {0u, 0u}, ph1[2] = {0u, 0u};
    u64t acc[GB];

#pragma unroll 1
    for (int t = 0; t <= Tn; t++) {
        const int cur = t & 1, nxt = cur ^ 1;
        const float* h0c = shh0 + cur * SLOTF;
        const float* h1c = shh1 + cur * SLOTF;

        // ---- phase A gate: shh0[cur] = h0_{t-1}
        if (t > 0) {
            if (tid == 0) {
                mbar_waitc(mb0a + cur * 8, ph0[cur]);
                mbar_expect(mb0a + cur * 8, EXPTX);   // arm next phase BEFORE our sends
            }
            ph0[cur] ^= 1u;
        }
        __syncthreads();

        if (t < Tn) {
            // mv0 = W_hh0 . h0_{t-1}
#pragma unroll
            for (int b = 0; b < GB; b++) acc[b] = 0ull;
            {
                const float* hc = h0c + kg * 256;
#pragma unroll
                for (int ii = 0; ii < 8; ii++) {
#pragma unroll
                    for (int b = 0; b < GB; b++) {
                        ulonglong2 h2 = *(const ulonglong2*)(hc + b * 32 + ii * 4);
                        acc[b] = fma2(w0[2 * ii],     h2.x, acc[b]);
                        acc[b] = fma2(w0[2 * ii + 1], h2.y, acc[b]);
                    }
                }
            }
#pragma unroll
            for (int b = 0; b < GB; b++) {
                float2 f = upk(acc[b]);
                part0[kg * 256 + b * 32 + j] = f.x + f.y;
            }
            __syncthreads();
            if (tid < 256) {
                float s0 = xpv, s1 = 0.f;
#pragma unroll
                for (int kk = 0; kk < 16; kk += 2) {
                    s0 += part0[kk * 256 + rb * 32 + rj];
                    s1 += part0[(kk + 1) * 256 + rb * 32 + rj];
                }
                float hn = tanhf(s0 + s1);
                shh0[nxt * SLOTF + slice * 256 + rb * 32 + rj] = hn;  // own region
                if (t + 1 < Tn) xpv = __ldg(g_xp + xbase + (size_t)(t + 1) * Hn);
            }
            __syncthreads();
            if (tid < NS - 1) {   // push our 1KB region to the 15 peers
                fence_async();
                unsigned src = sh0a + nxt * SLOTB + slice * REGB;
                bulk_s2s(mapa_u32(src, prank), src, REGB, mapa_u32(mb0a + nxt * 8, prank));
            }
        }

        // ---- phase B gate: shh1[cur] = h1_{t-2}
        if (t >= 1) {
            if (t >= 2) {
                if (tid == 0) {
                    mbar_waitc(mb1a + cur * 8, ph1[cur]);
                    mbar_expect(mb1a + cur * 8, EXPTX);
                }
                ph1[cur] ^= 1u;
            }
            __syncthreads();

            // mvB = W_hh1 . h1_{t-2}
#pragma unroll
            for (int b = 0; b < GB; b++) acc[b] = 0ull;
            {
                const float* hc = h1c + kg * 256;
#pragma unroll
                for (int ii = 0; ii < 8; ii++) {
#pragma unroll
                    for (int b = 0; b < GB; b++) {
                        ulonglong2 h2 = *(const ulonglong2*)(hc + b * 32 + ii * 4);
                        acc[b] = fma2(w1[2 * ii],     h2.x, acc[b]);
                        acc[b] = fma2(w1[2 * ii + 1], h2.y, acc[b]);
                    }
                }
            }
            // mvC = W_ih1 . h0_{t-1}
            {
                const float* wr = wih1 + j * WSTRIDE + kg * 32;
                const float* hc = h0c + kg * 256;
#pragma unroll
                for (int ii = 0; ii < 8; ii++) {
                    ulonglong2 w2 = *(const ulonglong2*)(wr + ii * 4);
#pragma unroll
                    for (int b = 0; b < GB; b++) {
                        ulonglong2 h2 = *(const ulonglong2*)(hc + b * 32 + ii * 4);
                        acc[b] = fma2(w2.x, h2.x, acc[b]);
                        acc[b] = fma2(w2.y, h2.y, acc[b]);
                    }
                }
            }
#pragma unroll
            for (int b = 0; b < GB; b++) {
                float2 f = upk(acc[b]);
                part1[kg * 256 + b * 32 + j] = f.x + f.y;
            }
            __syncthreads();
            if (tid < 256) {
                float s0 = bias1, s1 = 0.f;
#pragma unroll
                for (int kk = 0; kk < 16; kk += 2) {
                    s0 += part1[kk * 256 + rb * 32 + rj];
                    s1 += part1[(kk + 1) * 256 + rb * 32 + rj];
                }
                float hn = tanhf(s0 + s1);
                if (t < Tn) shh1[nxt * SLOTF + slice * 256 + rb * 32 + rj] = hn;
                else        g_hT[(group * GB + rb) * Hn + rcol] = hn;
            }
            __syncthreads();
            if (t < Tn && tid < NS - 1) {
                fence_async();
                unsigned src = sh1a + nxt * SLOTB + slice * REGB;
                bulk_s2s(mapa_u32(src, prank), src, REGB, mapa_u32(mb1a + nxt * 8, prank));
            }
        }
    }

    cluster_sync();   // drain: no CTA exits while peer copies may target its SMEM
}

// ---------------- final FC ------------------------------------------------------
__global__ __launch_bounds__(128) void fc_kernel(
    const float* __restrict__ Wfc, const float* __restrict__ bfc,
    float* __restrict__ out)
{
    __shared__ float hs[Hn];
    const int b = blockIdx.x, tid = threadIdx.x;
    ((float4*)hs)[tid] = *(const float4*)&g_hT[b * Hn + tid * 4];
    __syncthreads();
    const float4* wr = (const float4*)(Wfc + (size_t)tid * Hn);
    float acc = 0.f;
#pragma unroll 8
    for (int i = 0; i < Hn / 4; i++) {
        float4 w = __ldg(&wr[i]);
        float4 h = ((const float4*)hs)[i];
        acc += w.x * h.x + w.y * h.y + w.z * h.z + w.w * h.w;
    }
    out[b * On + tid] = acc + bfc[tid];
}

// ---------------- launcher ------------------------------------------------------
extern "C" void kernel_launch(void* const* d_in, const int* in_sizes, int n_in,
                              void* d_out, int out_size)
{
    (void)in_sizes; (void)n_in; (void)out_size;
    const float* x     = (const float*)d_in[0];
    const float* W_ih0 = (const float*)d_in[1];
    const float* W_hh0 = (const float*)d_in[2];
    const float* b_ih0 = (const float*)d_in[3];
    const float* b_hh0 = (const float*)d_in[4];
    const float* h0_0  = (const float*)d_in[5];
    const float* W_ih1 = (const float*)d_in[6];
    const float* W_hh1 = (const float*)d_in[7];
    const float* b_ih1 = (const float*)d_in[8];
    const float* b_hh1 = (const float*)d_in[9];
    const float* h0_1  = (const float*)d_in[10];
    const float* W_fc  = (const float*)d_in[11];
    const float* b_fc  = (const float*)d_in[12];
    float* out = (float*)d_out;

    const int fused_smem = (SC * WSTRIDE + 4 * SLOTF + 2 * SLOTF) * sizeof(float);
    cudaFuncSetAttribute(fused_rnn, cudaFuncAttributeMaxDynamicSharedMemorySize, fused_smem);
    cudaFuncSetAttribute(fused_rnn, cudaFuncAttributeNonPortableClusterSizeAllowed, 1);

    // xp0 = x @ W_ih0^T + b_ih0 + b_hh0
    sgemm_xp<<<dim3((Bn * Tn) / 128, Hn / 128), 256>>>(x, W_ih0, b_ih0, b_hh0);

    // fused skewed two-layer recurrence, DSMEM cluster exchange
    fused_rnn<<<NG * NS, NTHR, fused_smem>>>(W_hh0, W_ih1, W_hh1,
                                             b_ih1, b_hh1, h0_0, h0_1);

    // head
    fc_kernel<<<Bn, 128>>>(W_fc, b_fc, out);
}